// round 2
// baseline (speedup 1.0000x reference)
#include <cuda_runtime.h>
#include <cstdint>

// Problem constants
#define BB 4
#define HH 48
#define WW 48
#define CC 128
#define NWIN 144          // windows per batch (12x12)
#define NQ 16             // queries per window
#define NHEAD 8
#define HDIM 16
#define NKV 784           // 64 local + 576 mid + 144 glo

// ---------------- scratch (device globals; no allocation allowed) ----------
__device__ float g_F [BB*HH*WW*CC];      // raw features, pixel-major
__device__ float g_FN[BB*HH*WW*CC];      // layernormed features, pixel-major
__device__ float g_Q [BB*HH*WW*CC];      // queries per pixel
__device__ float g_KV[BB*HH*WW*256];     // per-pixel KV projection (K|V)
__device__ float g_KVmid[BB*24*24*256];  // 2x2 pooled KV
__device__ float g_KVglo[BB*12*12*256];  // 4x4 pooled KV

__device__ __forceinline__ float ex2f(float x) {
    float r;
    asm("ex2.approx.f32 %0, %1;" : "=f"(r) : "f"(x));
    return r;
}

// ============================================================================
// Kernel 0: transpose NCHW -> pixel-major + LayerNorm.  One warp per pixel.
// ============================================================================
__global__ void k0_ln(const float* __restrict__ feat,
                      const float* __restrict__ lnw,
                      const float* __restrict__ lnb) {
    int warp = (blockIdx.x * blockDim.x + threadIdx.x) >> 5;
    int lane = threadIdx.x & 31;
    if (warp >= BB*HH*WW) return;
    int b   = warp / (HH*WW);
    int rem = warp % (HH*WW);         // y*48 + x
    const float* src = feat + (size_t)b * CC * HH * WW + rem;

    float v[4];
    float s = 0.f, ss = 0.f;
#pragma unroll
    for (int i = 0; i < 4; i++) {
        int c = lane + 32*i;
        v[i] = src[(size_t)c * (HH*WW)];
        s  += v[i];
        ss += v[i]*v[i];
    }
#pragma unroll
    for (int o = 16; o; o >>= 1) {
        s  += __shfl_xor_sync(0xffffffffu, s,  o);
        ss += __shfl_xor_sync(0xffffffffu, ss, o);
    }
    float mean = s * (1.f/128.f);
    float var  = ss * (1.f/128.f) - mean*mean;
    float rstd = rsqrtf(var + 1e-5f);

    float* dF = g_F  + (size_t)warp * CC;
    float* dN = g_FN + (size_t)warp * CC;
#pragma unroll
    for (int i = 0; i < 4; i++) {
        int c = lane + 32*i;
        dF[c] = v[i];
        dN[c] = (v[i] - mean) * rstd * lnw[c] + lnb[c];
    }
}

// ============================================================================
// Kernel 1: fused GEMMs.
//   sub 0: Q  = FN @ q_w^T  + q_b            [9216,128]x[128,128]
//   sub 1: K  = F  @ kv_w[0:128]^T  + kv_b[0:128]
//   sub 2: V  = F  @ kv_w[128:256]^T + kv_b[128:256]
// Tile M=64, N=128, K chunked by 32.  256 threads, 4x8 microtile per thread.
// ============================================================================
#define MT 64
#define PADK 36

__global__ void k1_gemm(const float* __restrict__ qw, const float* __restrict__ qb,
                        const float* __restrict__ kvw, const float* __restrict__ kvb) {
    __shared__ float sA[MT][PADK];
    __shared__ float sB[128][PADK];

    int sub   = blockIdx.y;
    int mBase = blockIdx.x * MT;
    const float* A    = (sub == 0) ? g_FN : g_F;
    const float* Wm   = (sub == 0) ? qw : (kvw + (size_t)(sub-1)*128*128);
    const float* bias = (sub == 0) ? qb : (kvb + (sub-1)*128);

    int tid = threadIdx.x;
    int mg = tid & 15;      // 16 m-groups of 4 rows
    int ng = tid >> 4;      // 16 n-groups of 8 cols

    float acc[4][8];
#pragma unroll
    for (int m = 0; m < 4; m++)
#pragma unroll
        for (int n = 0; n < 8; n++) acc[m][n] = 0.f;

    for (int ck = 0; ck < 4; ck++) {
        __syncthreads();
        // fill A: 64 x 32  (64*32/4 = 512 float4 -> 2 per thread)
#pragma unroll
        for (int i = 0; i < 2; i++) {
            int f = tid + i*256;
            int pix = f >> 3, kq = f & 7;
            float4 val = *(const float4*)(A + (size_t)(mBase+pix)*128 + ck*32 + kq*4);
            *(float4*)&sA[pix][kq*4] = val;
        }
        // fill B: 128 x 32 (128*32/4 = 1024 float4 -> 4 per thread)
#pragma unroll
        for (int i = 0; i < 4; i++) {
            int f = tid + i*256;
            int row = f >> 3, kq = f & 7;
            float4 val = *(const float4*)(Wm + (size_t)row*128 + ck*32 + kq*4);
            *(float4*)&sB[row][kq*4] = val;
        }
        __syncthreads();

#pragma unroll
        for (int k4 = 0; k4 < 8; k4++) {
            float4 a0 = *(const float4*)&sA[mg*4+0][k4*4];
            float4 a1 = *(const float4*)&sA[mg*4+1][k4*4];
            float4 a2 = *(const float4*)&sA[mg*4+2][k4*4];
            float4 a3 = *(const float4*)&sA[mg*4+3][k4*4];
#pragma unroll
            for (int n = 0; n < 8; n++) {
                float4 bv = *(const float4*)&sB[ng*8+n][k4*4];
                acc[0][n] += a0.x*bv.x + a0.y*bv.y + a0.z*bv.z + a0.w*bv.w;
                acc[1][n] += a1.x*bv.x + a1.y*bv.y + a1.z*bv.z + a1.w*bv.w;
                acc[2][n] += a2.x*bv.x + a2.y*bv.y + a2.z*bv.z + a2.w*bv.w;
                acc[3][n] += a3.x*bv.x + a3.y*bv.y + a3.z*bv.z + a3.w*bv.w;
            }
        }
    }

    float4 bv0 = *(const float4*)(bias + ng*8);
    float4 bv1 = *(const float4*)(bias + ng*8 + 4);
    int stride = (sub == 0) ? 128 : 256;
    float* base = (sub == 0) ? (g_Q + ng*8) : (g_KV + (sub-1)*128 + ng*8);
#pragma unroll
    for (int m = 0; m < 4; m++) {
        float* dst = base + (size_t)(mBase + mg*4 + m) * stride;
        float4 r0 = make_float4(acc[m][0]+bv0.x, acc[m][1]+bv0.y, acc[m][2]+bv0.z, acc[m][3]+bv0.w);
        float4 r1 = make_float4(acc[m][4]+bv1.x, acc[m][5]+bv1.y, acc[m][6]+bv1.z, acc[m][7]+bv1.w);
        *(float4*)dst       = r0;
        *((float4*)dst + 1) = r1;
    }
}

// ============================================================================
// Kernel 2: pooled KV.  block = one token (mid: 2304 blocks, glo: 576 blocks),
// thread = one of 256 channels.
// ============================================================================
__global__ void k2_pool() {
    int t = blockIdx.x;
    int c = threadIdx.x;
    if (t < BB*576) {
        int b = t / 576, r = t % 576, my = r / 24, mx = r % 24;
        const float* base = g_KV + ((size_t)((b*48 + my*2)*48 + mx*2))*256 + c;
        float v = base[0] + base[256] + base[48*256] + base[48*256 + 256];
        g_KVmid[(size_t)t*256 + c] = v * 0.25f;
    } else {
        int t2 = t - BB*576;
        int b = t2 / 144, r = t2 % 144, gy = r / 12, gx = r % 12;
        float v = 0.f;
#pragma unroll
        for (int i = 0; i < 4; i++)
#pragma unroll
            for (int j = 0; j < 4; j++)
                v += g_KV[((size_t)((b*48 + gy*4 + i)*48 + gx*4 + j))*256 + c];
        g_KVglo[(size_t)t2*256 + c] = v * (1.f/16.f);
    }
}

// ============================================================================
// Kernel 3: attention (online softmax) + out projection + residual.
// One CTA per window (576).  warp h = head h.  lane -> (qi = lane/2, d-half).
// 49 tiles of 16 KV tokens streamed through smem.
// ============================================================================
#define TT 16

__global__ void __launch_bounds__(256)
k3_attn(const float* __restrict__ feat, const float* __restrict__ kvb,
        const float* __restrict__ ow,   const float* __restrict__ ob,
        float* __restrict__ out) {
    __shared__ float sK[TT][128];
    __shared__ float sV[TT][128];
    __shared__ float sAtt[NQ][132];
    __shared__ float sW[32][132];

    int w  = blockIdx.x;
    int b  = w / NWIN, wi = w % NWIN;
    int wy = wi / 12,  wx = wi % 12;
    int tid = threadIdx.x;
    int h    = tid >> 5;
    int lane = tid & 31;
    int qi   = lane >> 1;
    int dp   = lane & 1;

    // Q in registers, pre-scaled by (1/sqrt(hd)) * log2(e)
    const float SCALE = 0.25f * 1.4426950408889634f;
    int py = wy*4 + (qi >> 2), px = wx*4 + (qi & 3);
    int pix = (b*48 + py)*48 + px;
    const float* qsrc = g_Q + (size_t)pix*128 + h*16 + dp*8;
    float4 q0 = *(const float4*)qsrc;
    float4 q1 = *(const float4*)(qsrc + 4);
    float q[8] = { q0.x*SCALE, q0.y*SCALE, q0.z*SCALE, q0.w*SCALE,
                   q1.x*SCALE, q1.y*SCALE, q1.z*SCALE, q1.w*SCALE };

    float acc[8] = {0,0,0,0,0,0,0,0};
    float mrun = -1e30f, lsum = 0.f;

    // loader mapping: 16 tokens x 16 segments of 16 floats
    int lj  = tid >> 4;
    int seg = tid & 15;
    int c0  = seg * 16;

    const float* kb = &sK[0][h*16 + dp*8];
    const float* vb = &sV[0][h*16 + dp*8];

    for (int tile = 0; tile < 49; tile++) {
        __syncthreads();
        {
            int t = tile*16 + lj;
            const float* src;
            if (t < 64) {
                int dy = t >> 3, dx = t & 7;
                int y = wy*4 + dy - 2, x = wx*4 + dx - 2;
                if ((unsigned)y < 48u && (unsigned)x < 48u)
                    src = g_KV + ((size_t)((b*48 + y)*48 + x))*256;
                else
                    src = kvb;                         // zero token -> bias only
            } else if (t < 640) {
                src = g_KVmid + (size_t)(b*576 + (t-64))*256;
            } else {
                src = g_KVglo + (size_t)(b*144 + (t-640))*256;
            }
            float* dst = (c0 < 128) ? &sK[lj][c0] : &sV[lj][c0-128];
#pragma unroll
            for (int i = 0; i < 4; i++)
                *(float4*)(dst + i*4) = *(const float4*)(src + c0 + i*4);
        }
        __syncthreads();

        // scores for 16 tokens (each lane computes 8-d partial, pairs combine)
        float s[16];
#pragma unroll
        for (int j = 0; j < 16; j++) {
            float4 k0 = *(const float4*)(kb + j*128);
            float4 k1 = *(const float4*)(kb + j*128 + 4);
            float p = q[0]*k0.x + q[1]*k0.y + q[2]*k0.z + q[3]*k0.w
                    + q[4]*k1.x + q[5]*k1.y + q[6]*k1.z + q[7]*k1.w;
            s[j] = p + __shfl_xor_sync(0xffffffffu, p, 1);
        }
        float tmax = s[0];
#pragma unroll
        for (int j = 1; j < 16; j++) tmax = fmaxf(tmax, s[j]);
        float mnew = fmaxf(mrun, tmax);
        float corr = ex2f(mrun - mnew);
        mrun = mnew;
        lsum *= corr;
#pragma unroll
        for (int i = 0; i < 8; i++) acc[i] *= corr;

#pragma unroll
        for (int j = 0; j < 16; j++) {
            float p = ex2f(s[j] - mnew);
            lsum += p;
            float4 v0 = *(const float4*)(vb + j*128);
            float4 v1 = *(const float4*)(vb + j*128 + 4);
            acc[0] += p*v0.x; acc[1] += p*v0.y; acc[2] += p*v0.z; acc[3] += p*v0.w;
            acc[4] += p*v1.x; acc[5] += p*v1.y; acc[6] += p*v1.z; acc[7] += p*v1.w;
        }
    }

    // normalized attended -> smem
    float inv = 1.f / lsum;
    float* arow = &sAtt[qi][h*16 + dp*8];
#pragma unroll
    for (int i = 0; i < 8; i++) arow[i] = acc[i]*inv;
    __syncthreads();

    // out projection: thread = (aqi, og); per 32-row weight chunk compute 2 cols
    int aqi = tid >> 4;
    int og  = tid & 15;
    float o[8];
#pragma unroll
    for (int ch = 0; ch < 4; ch++) {
        // load 32x128 weight chunk: 1024 float4, 4 per thread
#pragma unroll
        for (int i = 0; i < 4; i++) {
            int f = tid + i*256;           // 0..1023
            int row = f >> 5, quad = f & 31;
            *(float4*)&sW[row][quad*4] =
                *(const float4*)(ow + (size_t)(ch*32 + row)*128 + quad*4);
        }
        __syncthreads();
        float ra = 0.f, rb = 0.f;
#pragma unroll
        for (int k4 = 0; k4 < 32; k4++) {
            float4 a  = *(const float4*)&sAtt[aqi][k4*4];
            float4 wa = *(const float4*)&sW[og][k4*4];
            float4 wb = *(const float4*)&sW[og+16][k4*4];
            ra += a.x*wa.x + a.y*wa.y + a.z*wa.z + a.w*wa.w;
            rb += a.x*wb.x + a.y*wb.y + a.z*wb.z + a.w*wb.w;
        }
        o[ch*2]   = ra;
        o[ch*2+1] = rb;
        __syncthreads();
    }

    // residual add + NCHW scatter store
    int py2 = wy*4 + (aqi >> 2), px2 = wx*4 + (aqi & 3);
#pragma unroll
    for (int ch = 0; ch < 4; ch++) {
#pragma unroll
        for (int u = 0; u < 2; u++) {
            int oc = ch*32 + u*16 + og;
            size_t gidx = (((size_t)b*128 + oc)*48 + py2)*48 + px2;
            out[gidx] = o[ch*2+u] + ob[oc] + feat[gidx];
        }
    }
}

// ============================================================================
extern "C" void kernel_launch(void* const* d_in, const int* in_sizes, int n_in,
                              void* d_out, int out_size) {
    const float* feat = (const float*)d_in[0];
    const float* lnw  = (const float*)d_in[1];
    const float* lnb  = (const float*)d_in[2];
    const float* qw   = (const float*)d_in[3];
    const float* qb   = (const float*)d_in[4];
    const float* kvw  = (const float*)d_in[5];
    const float* kvb  = (const float*)d_in[6];
    const float* ow   = (const float*)d_in[7];
    const float* ob   = (const float*)d_in[8];
    float* out = (float*)d_out;

    k0_ln<<<1152, 256>>>(feat, lnw, lnb);            // 9216 pixels, warp each
    k1_gemm<<<dim3(144, 3), 256>>>(qw, qb, kvw, kvb);
    k2_pool<<<2880, 256>>>();                        // 2304 mid + 576 glo
    k3_attn<<<576, 256>>>(feat, kvb, ow, ob, out);
}

// round 3
// speedup vs baseline: 1.2735x; 1.2735x over previous
#include <cuda_runtime.h>
#include <cstdint>

// Problem constants
#define BB 4
#define HH 48
#define WW 48
#define CC 128
#define NWIN 144
#define NQ 16
#define NHEAD 8
#define HDIM 16

typedef unsigned long long u64;

// ---------------- scratch (device globals; no allocation allowed) ----------
__device__ float g_F [BB*HH*WW*CC];      // raw features, pixel-major
__device__ float g_FN[BB*HH*WW*CC];      // layernormed features, pixel-major
__device__ float g_Q [BB*HH*WW*CC];      // queries per pixel
__device__ float g_KV[BB*HH*WW*256];     // per-pixel KV projection (K|V)
__device__ float g_KVmid[BB*24*24*256];  // 2x2 pooled KV
__device__ float g_KVglo[BB*12*12*256];  // 4x4 pooled KV

__device__ __forceinline__ float ex2f(float x) {
    float r; asm("ex2.approx.f32 %0, %1;" : "=f"(r) : "f"(x)); return r;
}
__device__ __forceinline__ u64 ffma2(u64 a, u64 b, u64 c) {
    u64 d; asm("fma.rn.f32x2 %0,%1,%2,%3;" : "=l"(d) : "l"(a), "l"(b), "l"(c)); return d;
}
__device__ __forceinline__ u64 fmul2(u64 a, u64 b) {
    u64 d; asm("mul.rn.f32x2 %0,%1,%2;" : "=l"(d) : "l"(a), "l"(b)); return d;
}
__device__ __forceinline__ u64 pk2(float lo, float hi) {
    u64 d; asm("mov.b64 %0,{%1,%2};" : "=l"(d) : "f"(lo), "f"(hi)); return d;
}
__device__ __forceinline__ void up2(u64 v, float& lo, float& hi) {
    asm("mov.b64 {%0,%1},%2;" : "=f"(lo), "=f"(hi) : "l"(v));
}

// ============================================================================
// Kernel 0: transpose NCHW -> pixel-major + LayerNorm.  One warp per pixel.
// ============================================================================
__global__ void k0_ln(const float* __restrict__ feat,
                      const float* __restrict__ lnw,
                      const float* __restrict__ lnb) {
    int warp = (blockIdx.x * blockDim.x + threadIdx.x) >> 5;
    int lane = threadIdx.x & 31;
    if (warp >= BB*HH*WW) return;
    int b   = warp / (HH*WW);
    int rem = warp % (HH*WW);
    const float* src = feat + (size_t)b * CC * HH * WW + rem;

    float v[4];
    float s = 0.f, ss = 0.f;
#pragma unroll
    for (int i = 0; i < 4; i++) {
        int c = lane + 32*i;
        v[i] = src[(size_t)c * (HH*WW)];
        s  += v[i];
        ss += v[i]*v[i];
    }
#pragma unroll
    for (int o = 16; o; o >>= 1) {
        s  += __shfl_xor_sync(0xffffffffu, s,  o);
        ss += __shfl_xor_sync(0xffffffffu, ss, o);
    }
    float mean = s * (1.f/128.f);
    float var  = ss * (1.f/128.f) - mean*mean;
    float rstd = rsqrtf(var + 1e-5f);

    float* dF = g_F  + (size_t)warp * CC;
    float* dN = g_FN + (size_t)warp * CC;
#pragma unroll
    for (int i = 0; i < 4; i++) {
        int c = lane + 32*i;
        dF[c] = v[i];
        dN[c] = (v[i] - mean) * rstd * lnw[c] + lnb[c];
    }
}

// ============================================================================
// Kernel 1: fused GEMMs (Q / K / V projections).  Unchanged from R2.
// ============================================================================
#define MT 64
#define PADK 36

__global__ void k1_gemm(const float* __restrict__ qw, const float* __restrict__ qb,
                        const float* __restrict__ kvw, const float* __restrict__ kvb) {
    __shared__ float sA[MT][PADK];
    __shared__ float sB[128][PADK];

    int sub   = blockIdx.y;
    int mBase = blockIdx.x * MT;
    const float* A    = (sub == 0) ? g_FN : g_F;
    const float* Wm   = (sub == 0) ? qw : (kvw + (size_t)(sub-1)*128*128);
    const float* bias = (sub == 0) ? qb : (kvb + (sub-1)*128);

    int tid = threadIdx.x;
    int mg = tid & 15;
    int ng = tid >> 4;

    float acc[4][8];
#pragma unroll
    for (int m = 0; m < 4; m++)
#pragma unroll
        for (int n = 0; n < 8; n++) acc[m][n] = 0.f;

    for (int ck = 0; ck < 4; ck++) {
        __syncthreads();
#pragma unroll
        for (int i = 0; i < 2; i++) {
            int f = tid + i*256;
            int pix = f >> 3, kq = f & 7;
            float4 val = *(const float4*)(A + (size_t)(mBase+pix)*128 + ck*32 + kq*4);
            *(float4*)&sA[pix][kq*4] = val;
        }
#pragma unroll
        for (int i = 0; i < 4; i++) {
            int f = tid + i*256;
            int row = f >> 3, kq = f & 7;
            float4 val = *(const float4*)(Wm + (size_t)row*128 + ck*32 + kq*4);
            *(float4*)&sB[row][kq*4] = val;
        }
        __syncthreads();

#pragma unroll
        for (int k4 = 0; k4 < 8; k4++) {
            float4 a0 = *(const float4*)&sA[mg*4+0][k4*4];
            float4 a1 = *(const float4*)&sA[mg*4+1][k4*4];
            float4 a2 = *(const float4*)&sA[mg*4+2][k4*4];
            float4 a3 = *(const float4*)&sA[mg*4+3][k4*4];
#pragma unroll
            for (int n = 0; n < 8; n++) {
                float4 bv = *(const float4*)&sB[ng*8+n][k4*4];
                acc[0][n] += a0.x*bv.x + a0.y*bv.y + a0.z*bv.z + a0.w*bv.w;
                acc[1][n] += a1.x*bv.x + a1.y*bv.y + a1.z*bv.z + a1.w*bv.w;
                acc[2][n] += a2.x*bv.x + a2.y*bv.y + a2.z*bv.z + a2.w*bv.w;
                acc[3][n] += a3.x*bv.x + a3.y*bv.y + a3.z*bv.z + a3.w*bv.w;
            }
        }
    }

    float4 bv0 = *(const float4*)(bias + ng*8);
    float4 bv1 = *(const float4*)(bias + ng*8 + 4);
    int stride = (sub == 0) ? 128 : 256;
    float* base = (sub == 0) ? (g_Q + ng*8) : (g_KV + (sub-1)*128 + ng*8);
#pragma unroll
    for (int m = 0; m < 4; m++) {
        float* dst = base + (size_t)(mBase + mg*4 + m) * stride;
        float4 r0 = make_float4(acc[m][0]+bv0.x, acc[m][1]+bv0.y, acc[m][2]+bv0.z, acc[m][3]+bv0.w);
        float4 r1 = make_float4(acc[m][4]+bv1.x, acc[m][5]+bv1.y, acc[m][6]+bv1.z, acc[m][7]+bv1.w);
        *(float4*)dst       = r0;
        *((float4*)dst + 1) = r1;
    }
}

// ============================================================================
// Kernel 2: pooled KV.  Unchanged from R2.
// ============================================================================
__global__ void k2_pool() {
    int t = blockIdx.x;
    int c = threadIdx.x;
    if (t < BB*576) {
        int b = t / 576, r = t % 576, my = r / 24, mx = r % 24;
        const float* base = g_KV + ((size_t)((b*48 + my*2)*48 + mx*2))*256 + c;
        float v = base[0] + base[256] + base[48*256] + base[48*256 + 256];
        g_KVmid[(size_t)t*256 + c] = v * 0.25f;
    } else {
        int t2 = t - BB*576;
        int b = t2 / 144, r = t2 % 144, gy = r / 12, gx = r % 12;
        float v = 0.f;
#pragma unroll
        for (int i = 0; i < 4; i++)
#pragma unroll
            for (int j = 0; j < 4; j++)
                v += g_KV[((size_t)((b*48 + gy*4 + i)*48 + gx*4 + j))*256 + c];
        g_KVglo[(size_t)t2*256 + c] = v * (1.f/16.f);
    }
}

// ============================================================================
// Kernel 3 v2: attention for a 2x2 GROUP of windows per CTA.
//   grid = 144 CTAs (= 4 batches x 36 groups), 512 threads = 16 warps.
//   warp = (head h = warp&7, token-half = warp>>3).
//   Each lane owns 2 queries (qg0=lane, qg1=lane+32) of the group's 64.
//   K/V head slices read directly from gmem (uniform-address broadcast LDG).
//   61 tiles of 16 tokens: 16 local (masked per window) + 36 mid + 9 glo,
//   split odd/even between the two halves; merged via smem; fused out-proj.
// ============================================================================
__global__ void __launch_bounds__(512, 1)
k3_attn(const float* __restrict__ feat, const float* __restrict__ kvb,
        const float* __restrict__ ow,   const float* __restrict__ ob,
        float* __restrict__ out) {
    __shared__ float sAtt[64][132];
    __shared__ float sL[64][8];
    __shared__ float sW[16][132];

    int cta = blockIdx.x;
    int b = cta / 36, g = cta % 36;
    int gy = g / 6, gx = g % 6;
    int tid  = threadIdx.x;
    int lane = tid & 31;
    int warp = tid >> 5;
    int h = warp & 7, half = warp >> 3;

    int qg0 = lane, qg1 = lane + 32;
    int wgA = qg0 >> 4, wgB = qg1 >> 4;    // window-in-group of each query

    const float SC = 0.25f * 1.4426950408889634f;   // 1/sqrt(hd) * log2(e)
    u64 SC2 = pk2(SC, SC);

    // ---- load 2 queries (16 dims each) as f32x2 pairs, pre-scaled ----
    u64 q0[8], q1[8];
    {
        int qi = qg0 & 15;
        int wy = gy*2 + (wgA>>1), wx = gx*2 + (wgA&1);
        int py = wy*4 + (qi>>2), px = wx*4 + (qi&3);
        const longlong2* qp = (const longlong2*)(g_Q + ((size_t)((b*48+py)*48+px))*128 + h*16);
#pragma unroll
        for (int i = 0; i < 4; i++) {
            longlong2 t2 = qp[i];
            q0[2*i]   = fmul2((u64)t2.x, SC2);
            q0[2*i+1] = fmul2((u64)t2.y, SC2);
        }
    }
    {
        int qi = qg1 & 15;
        int wy = gy*2 + (wgB>>1), wx = gx*2 + (wgB&1);
        int py = wy*4 + (qi>>2), px = wx*4 + (qi&3);
        const longlong2* qp = (const longlong2*)(g_Q + ((size_t)((b*48+py)*48+px))*128 + h*16);
#pragma unroll
        for (int i = 0; i < 4; i++) {
            longlong2 t2 = qp[i];
            q1[2*i]   = fmul2((u64)t2.x, SC2);
            q1[2*i+1] = fmul2((u64)t2.y, SC2);
        }
    }

    u64 acc0[8], acc1[8];
#pragma unroll
    for (int i = 0; i < 8; i++) { acc0[i] = 0ull; acc1[i] = 0ull; }
    float ls0 = 0.f, ls1 = 0.f;

    // ---- main loop: this half's tiles (stride 2 over 61 tiles) ----
    for (int t = half; t < 61; t += 2) {
        float mb0f = 0.f, mb1f = 0.f;
        const float* sharedBase = nullptr;
        int loc_wy = 0, loc_wx = 0, st = 0;
        bool isLocal = (t < 16);
        if (isLocal) {
            int wgl = t >> 2; st = t & 3;
            loc_wy = gy*2 + (wgl>>1); loc_wx = gx*2 + (wgl&1);
            mb0f = (wgA == wgl) ? 0.f : -1e30f;
            mb1f = (wgB == wgl) ? 0.f : -1e30f;
        } else if (t < 52) {
            sharedBase = g_KVmid + ((size_t)(b*576 + (t-16)*16))*256;
        } else {
            sharedBase = g_KVglo + ((size_t)(b*144 + (t-52)*16))*256;
        }
        u64 mb0 = pk2(mb0f, 0.f), mb1 = pk2(mb1f, 0.f);

#pragma unroll 2
        for (int j = 0; j < 16; j++) {
            const float* src;
            if (isLocal) {
                int idx = st*16 + j;
                int y = loc_wy*4 + (idx>>3) - 2;
                int x = loc_wx*4 + (idx&7)  - 2;
                src = ((unsigned)y < 48u && (unsigned)x < 48u)
                    ? (g_KV + ((size_t)((b*48+y)*48+x))*256) : kvb;
            } else {
                src = sharedBase + j*256;
            }
            const longlong2* kp = (const longlong2*)(src + h*16);
            longlong2 ka = kp[0], kb2 = kp[1], kc = kp[2], kd = kp[3];

            u64 d0 = ffma2(q0[0], (u64)ka.x,  mb0);
            d0 = ffma2(q0[1], (u64)ka.y,  d0);
            d0 = ffma2(q0[2], (u64)kb2.x, d0);
            d0 = ffma2(q0[3], (u64)kb2.y, d0);
            d0 = ffma2(q0[4], (u64)kc.x,  d0);
            d0 = ffma2(q0[5], (u64)kc.y,  d0);
            d0 = ffma2(q0[6], (u64)kd.x,  d0);
            d0 = ffma2(q0[7], (u64)kd.y,  d0);
            u64 d1 = ffma2(q1[0], (u64)ka.x,  mb1);
            d1 = ffma2(q1[1], (u64)ka.y,  d1);
            d1 = ffma2(q1[2], (u64)kb2.x, d1);
            d1 = ffma2(q1[3], (u64)kb2.y, d1);
            d1 = ffma2(q1[4], (u64)kc.x,  d1);
            d1 = ffma2(q1[5], (u64)kc.y,  d1);
            d1 = ffma2(q1[6], (u64)kd.x,  d1);
            d1 = ffma2(q1[7], (u64)kd.y,  d1);

            float a, bb;
            up2(d0, a, bb); float s0 = a + bb;
            up2(d1, a, bb); float s1 = a + bb;
            float p0 = ex2f(s0), p1 = ex2f(s1);
            ls0 += p0; ls1 += p1;
            u64 P0 = pk2(p0, p0), P1 = pk2(p1, p1);

            const longlong2* vp = (const longlong2*)(src + 128 + h*16);
            longlong2 va = vp[0], vb2 = vp[1], vc = vp[2], vd = vp[3];
            acc0[0] = ffma2(P0, (u64)va.x,  acc0[0]);
            acc0[1] = ffma2(P0, (u64)va.y,  acc0[1]);
            acc0[2] = ffma2(P0, (u64)vb2.x, acc0[2]);
            acc0[3] = ffma2(P0, (u64)vb2.y, acc0[3]);
            acc0[4] = ffma2(P0, (u64)vc.x,  acc0[4]);
            acc0[5] = ffma2(P0, (u64)vc.y,  acc0[5]);
            acc0[6] = ffma2(P0, (u64)vd.x,  acc0[6]);
            acc0[7] = ffma2(P0, (u64)vd.y,  acc0[7]);
            acc1[0] = ffma2(P1, (u64)va.x,  acc1[0]);
            acc1[1] = ffma2(P1, (u64)va.y,  acc1[1]);
            acc1[2] = ffma2(P1, (u64)vb2.x, acc1[2]);
            acc1[3] = ffma2(P1, (u64)vb2.y, acc1[3]);
            acc1[4] = ffma2(P1, (u64)vc.x,  acc1[4]);
            acc1[5] = ffma2(P1, (u64)vc.y,  acc1[5]);
            acc1[6] = ffma2(P1, (u64)vd.x,  acc1[6]);
            acc1[7] = ffma2(P1, (u64)vd.y,  acc1[7]);
        }
    }

    // ---- merge the two token-halves via smem, normalize ----
    if (half == 0) {
        float* r0 = &sAtt[qg0][h*16];
        float* r1 = &sAtt[qg1][h*16];
#pragma unroll
        for (int i = 0; i < 8; i++) {
            float a, bb;
            up2(acc0[i], a, bb); r0[2*i] = a; r0[2*i+1] = bb;
            up2(acc1[i], a, bb); r1[2*i] = a; r1[2*i+1] = bb;
        }
        sL[qg0][h] = ls0;
        sL[qg1][h] = ls1;
    }
    __syncthreads();
    if (half == 1) {
        float inv0 = 1.f / (sL[qg0][h] + ls0);
        float inv1 = 1.f / (sL[qg1][h] + ls1);
        float* r0 = &sAtt[qg0][h*16];
        float* r1 = &sAtt[qg1][h*16];
#pragma unroll
        for (int i = 0; i < 8; i++) {
            float a, bb;
            up2(acc0[i], a, bb);
            r0[2*i]   = (r0[2*i]   + a ) * inv0;
            r0[2*i+1] = (r0[2*i+1] + bb) * inv0;
            up2(acc1[i], a, bb);
            r1[2*i]   = (r1[2*i]   + a ) * inv1;
            r1[2*i+1] = (r1[2*i+1] + bb) * inv1;
        }
    }
    __syncthreads();

    // ---- out projection: thread = (aqi = tid>>3, og = tid&7) -> 16 channels
    int aqi = tid >> 3, og = tid & 7;
    float o[16];
#pragma unroll 1
    for (int ch = 0; ch < 8; ch++) {
        {
            int row = tid >> 5, quad = tid & 31;
            *(float4*)&sW[row][quad*4] =
                *(const float4*)(ow + (size_t)(ch*16 + row)*128 + quad*4);
        }
        __syncthreads();
        u64 r0p = 0ull, r1p = 0ull;
#pragma unroll
        for (int k4 = 0; k4 < 32; k4++) {
            longlong2 av = *(const longlong2*)&sAtt[aqi][k4*4];
            longlong2 w0 = *(const longlong2*)&sW[og][k4*4];
            longlong2 w1 = *(const longlong2*)&sW[og+8][k4*4];
            r0p = ffma2((u64)av.x, (u64)w0.x, r0p);
            r0p = ffma2((u64)av.y, (u64)w0.y, r0p);
            r1p = ffma2((u64)av.x, (u64)w1.x, r1p);
            r1p = ffma2((u64)av.y, (u64)w1.y, r1p);
        }
        float a, bb;
        up2(r0p, a, bb); o[ch*2]   = a + bb;
        up2(r1p, a, bb); o[ch*2+1] = a + bb;
        __syncthreads();
    }

    // ---- residual add + NCHW scatter store ----
    {
        int qi = aqi & 15, wg = aqi >> 4;
        int wy = gy*2 + (wg>>1), wx = gx*2 + (wg&1);
        int py = wy*4 + (qi>>2), px = wx*4 + (qi&3);
#pragma unroll
        for (int ch = 0; ch < 8; ch++) {
#pragma unroll
            for (int u2 = 0; u2 < 2; u2++) {
                int oc = ch*16 + u2*8 + og;
                size_t gi = (((size_t)b*128 + oc)*48 + py)*48 + px;
                out[gi] = o[ch*2+u2] + ob[oc] + feat[gi];
            }
        }
    }
}

// ============================================================================
extern "C" void kernel_launch(void* const* d_in, const int* in_sizes, int n_in,
                              void* d_out, int out_size) {
    const float* feat = (const float*)d_in[0];
    const float* lnw  = (const float*)d_in[1];
    const float* lnb  = (const float*)d_in[2];
    const float* qw   = (const float*)d_in[3];
    const float* qb   = (const float*)d_in[4];
    const float* kvw  = (const float*)d_in[5];
    const float* kvb  = (const float*)d_in[6];
    const float* ow   = (const float*)d_in[7];
    const float* ob   = (const float*)d_in[8];
    float* out = (float*)d_out;

    k0_ln<<<1152, 256>>>(feat, lnw, lnb);
    k1_gemm<<<dim3(144, 3), 256>>>(qw, qb, kvw, kvb);
    k2_pool<<<2880, 256>>>();
    k3_attn<<<144, 512>>>(feat, kvb, ow, ob, out);
}

// round 4
// speedup vs baseline: 1.5013x; 1.1790x over previous
#include <cuda_runtime.h>
#include <cstdint>

// Problem constants
#define BB 4
#define HH 48
#define WW 48
#define CC 128
#define NWIN 144
#define NHEAD 8

typedef unsigned long long u64;

// ---------------- scratch (device globals; no allocation allowed) ----------
__device__ float g_F [BB*HH*WW*CC];      // raw features, pixel-major
__device__ float g_FN[BB*HH*WW*CC];      // layernormed features, pixel-major
__device__ float g_Q [BB*HH*WW*CC];      // queries per pixel
__device__ float g_KV[BB*HH*WW*256];     // per-pixel KV projection (K|V)
__device__ float g_KVmid[BB*24*24*256];  // 2x2 pooled KV
__device__ float g_KVglo[BB*12*12*256];  // 4x4 pooled KV

__device__ __forceinline__ float ex2f(float x) {
    float r; asm("ex2.approx.f32 %0, %1;" : "=f"(r) : "f"(x)); return r;
}
__device__ __forceinline__ u64 ffma2(u64 a, u64 b, u64 c) {
    u64 d; asm("fma.rn.f32x2 %0,%1,%2,%3;" : "=l"(d) : "l"(a), "l"(b), "l"(c)); return d;
}
__device__ __forceinline__ u64 fmul2(u64 a, u64 b) {
    u64 d; asm("mul.rn.f32x2 %0,%1,%2;" : "=l"(d) : "l"(a), "l"(b)); return d;
}
__device__ __forceinline__ u64 pk2(float lo, float hi) {
    u64 d; asm("mov.b64 %0,{%1,%2};" : "=l"(d) : "f"(lo), "f"(hi)); return d;
}
__device__ __forceinline__ void up2(u64 v, float& lo, float& hi) {
    asm("mov.b64 {%0,%1},%2;" : "=f"(lo), "=f"(hi) : "l"(v));
}
__device__ __forceinline__ void cp16(uint32_t dst, const float* src) {
    asm volatile("cp.async.cg.shared.global [%0], [%1], 16;" :: "r"(dst), "l"(src));
}

// ============================================================================
// Kernel 0: transpose NCHW -> pixel-major + LayerNorm.  One warp per pixel.
// ============================================================================
__global__ void k0_ln(const float* __restrict__ feat,
                      const float* __restrict__ lnw,
                      const float* __restrict__ lnb) {
    int warp = (blockIdx.x * blockDim.x + threadIdx.x) >> 5;
    int lane = threadIdx.x & 31;
    if (warp >= BB*HH*WW) return;
    int b   = warp / (HH*WW);
    int rem = warp % (HH*WW);
    const float* src = feat + (size_t)b * CC * HH * WW + rem;

    float v[4];
    float s = 0.f, ss = 0.f;
#pragma unroll
    for (int i = 0; i < 4; i++) {
        int c = lane + 32*i;
        v[i] = src[(size_t)c * (HH*WW)];
        s  += v[i];
        ss += v[i]*v[i];
    }
#pragma unroll
    for (int o = 16; o; o >>= 1) {
        s  += __shfl_xor_sync(0xffffffffu, s,  o);
        ss += __shfl_xor_sync(0xffffffffu, ss, o);
    }
    float mean = s * (1.f/128.f);
    float var  = ss * (1.f/128.f) - mean*mean;
    float rstd = rsqrtf(var + 1e-5f);

    float* dF = g_F  + (size_t)warp * CC;
    float* dN = g_FN + (size_t)warp * CC;
#pragma unroll
    for (int i = 0; i < 4; i++) {
        int c = lane + 32*i;
        dF[c] = v[i];
        dN[c] = (v[i] - mean) * rstd * lnw[c] + lnb[c];
    }
}

// ============================================================================
// Kernel 1: fused GEMMs (Q / K / V projections).  Unchanged.
// ============================================================================
#define MT 64
#define PADK 36

__global__ void k1_gemm(const float* __restrict__ qw, const float* __restrict__ qb,
                        const float* __restrict__ kvw, const float* __restrict__ kvb) {
    __shared__ float sA[MT][PADK];
    __shared__ float sB[128][PADK];

    int sub   = blockIdx.y;
    int mBase = blockIdx.x * MT;
    const float* A    = (sub == 0) ? g_FN : g_F;
    const float* Wm   = (sub == 0) ? qw : (kvw + (size_t)(sub-1)*128*128);
    const float* bias = (sub == 0) ? qb : (kvb + (sub-1)*128);

    int tid = threadIdx.x;
    int mg = tid & 15;
    int ng = tid >> 4;

    float acc[4][8];
#pragma unroll
    for (int m = 0; m < 4; m++)
#pragma unroll
        for (int n = 0; n < 8; n++) acc[m][n] = 0.f;

    for (int ck = 0; ck < 4; ck++) {
        __syncthreads();
#pragma unroll
        for (int i = 0; i < 2; i++) {
            int f = tid + i*256;
            int pix = f >> 3, kq = f & 7;
            float4 val = *(const float4*)(A + (size_t)(mBase+pix)*128 + ck*32 + kq*4);
            *(float4*)&sA[pix][kq*4] = val;
        }
#pragma unroll
        for (int i = 0; i < 4; i++) {
            int f = tid + i*256;
            int row = f >> 3, kq = f & 7;
            float4 val = *(const float4*)(Wm + (size_t)row*128 + ck*32 + kq*4);
            *(float4*)&sB[row][kq*4] = val;
        }
        __syncthreads();

#pragma unroll
        for (int k4 = 0; k4 < 8; k4++) {
            float4 a0 = *(const float4*)&sA[mg*4+0][k4*4];
            float4 a1 = *(const float4*)&sA[mg*4+1][k4*4];
            float4 a2 = *(const float4*)&sA[mg*4+2][k4*4];
            float4 a3 = *(const float4*)&sA[mg*4+3][k4*4];
#pragma unroll
            for (int n = 0; n < 8; n++) {
                float4 bv = *(const float4*)&sB[ng*8+n][k4*4];
                acc[0][n] += a0.x*bv.x + a0.y*bv.y + a0.z*bv.z + a0.w*bv.w;
                acc[1][n] += a1.x*bv.x + a1.y*bv.y + a1.z*bv.z + a1.w*bv.w;
                acc[2][n] += a2.x*bv.x + a2.y*bv.y + a2.z*bv.z + a2.w*bv.w;
                acc[3][n] += a3.x*bv.x + a3.y*bv.y + a3.z*bv.z + a3.w*bv.w;
            }
        }
    }

    float4 bv0 = *(const float4*)(bias + ng*8);
    float4 bv1 = *(const float4*)(bias + ng*8 + 4);
    int stride = (sub == 0) ? 128 : 256;
    float* base = (sub == 0) ? (g_Q + ng*8) : (g_KV + (sub-1)*128 + ng*8);
#pragma unroll
    for (int m = 0; m < 4; m++) {
        float* dst = base + (size_t)(mBase + mg*4 + m) * stride;
        float4 r0 = make_float4(acc[m][0]+bv0.x, acc[m][1]+bv0.y, acc[m][2]+bv0.z, acc[m][3]+bv0.w);
        float4 r1 = make_float4(acc[m][4]+bv1.x, acc[m][5]+bv1.y, acc[m][6]+bv1.z, acc[m][7]+bv1.w);
        *(float4*)dst       = r0;
        *((float4*)dst + 1) = r1;
    }
}

// ============================================================================
// Kernel 2: pooled KV.  Unchanged.
// ============================================================================
__global__ void k2_pool() {
    int t = blockIdx.x;
    int c = threadIdx.x;
    if (t < BB*576) {
        int b = t / 576, r = t % 576, my = r / 24, mx = r % 24;
        const float* base = g_KV + ((size_t)((b*48 + my*2)*48 + mx*2))*256 + c;
        float v = base[0] + base[256] + base[48*256] + base[48*256 + 256];
        g_KVmid[(size_t)t*256 + c] = v * 0.25f;
    } else {
        int t2 = t - BB*576;
        int b = t2 / 144, r = t2 % 144, gy = r / 12, gx = r % 12;
        float v = 0.f;
#pragma unroll
        for (int i = 0; i < 4; i++)
#pragma unroll
            for (int j = 0; j < 4; j++)
                v += g_KV[((size_t)((b*48 + gy*4 + i)*48 + gx*4 + j))*256 + c];
        g_KVglo[(size_t)t2*256 + c] = v * (1.f/16.f);
    }
}

// ============================================================================
// Kernel 3 v3: attention for a 2x2 window group, cp.async-staged KV tiles.
//   grid = 144 CTAs, 512 threads = 16 warps = 8 heads x 2 query-halves.
//   Lane owns ONE query (all 976 group tokens); tiles of 16 tokens staged
//   into a double-buffered smem ring with cp.async; LDS broadcast reads.
//   Warps skip local tiles belonging to the other query-half's windows.
// ============================================================================
#define NTILE 61

__global__ void __launch_bounds__(512, 1)
k3_attn(const float* __restrict__ feat, const float* __restrict__ kvb,
        const float* __restrict__ ow,   const float* __restrict__ ob,
        float* __restrict__ out) {
    __shared__ union {
        float kv[2][16][256];                      // 32 KB  (mainloop)
        struct { float att[64][132]; float w[16][132]; } e;  // 42 KB (epilogue)
    } sm;

    int cta = blockIdx.x;
    int b = cta / 36, g = cta % 36;
    int gy = g / 6, gx = g % 6;
    int tid  = threadIdx.x;
    int lane = tid & 31;
    int warp = tid >> 5;
    int h = warp & 7, qh = warp >> 3;

    int qg = qh*32 + lane;         // query slot in group (0..63)
    int wg = qg >> 4;              // this query's window-in-group (0..3)

    const float SC = 0.25f * 1.4426950408889634f;
    u64 SC2 = pk2(SC, SC);

    // ---- load this lane's query (16 dims) pre-scaled ----
    u64 q[8];
    {
        int qi = qg & 15;
        int wy = gy*2 + (wg>>1), wx = gx*2 + (wg&1);
        int py = wy*4 + (qi>>2), px = wx*4 + (qi&3);
        const longlong2* qp = (const longlong2*)(g_Q + ((size_t)((b*48+py)*48+px))*128 + h*16);
#pragma unroll
        for (int i = 0; i < 4; i++) {
            longlong2 t2 = qp[i];
            q[2*i]   = fmul2((u64)t2.x, SC2);
            q[2*i+1] = fmul2((u64)t2.y, SC2);
        }
    }

    u64 acc[8];
#pragma unroll
    for (int i = 0; i < 8; i++) acc[i] = 0ull;
    float ls = 0.f;

    // staging role: 32 threads per token row, 8 floats (32 B) each
    int srow = tid >> 5;           // token row 0..15
    int scol = (tid & 31) * 8;     // float offset 0..248

    // stage tile tt into buffer buf
    auto stage = [&](int tt, int buf) {
        const float* src;
        if (tt < 16) {
            int wgl = tt >> 2, st = tt & 3;
            int idx = st*16 + srow;
            int y = (gy*2 + (wgl>>1))*4 + (idx>>3) - 2;
            int x = (gx*2 + (wgl&1))*4  + (idx&7)  - 2;
            src = ((unsigned)y < 48u && (unsigned)x < 48u)
                ? (g_KV + ((size_t)((b*48+y)*48+x))*256) : kvb;
        } else if (tt < 52) {
            src = g_KVmid + ((size_t)(b*576 + (tt-16)*16 + srow))*256;
        } else {
            src = g_KVglo + ((size_t)(b*144 + (tt-52)*16 + srow))*256;
        }
        uint32_t dst = (uint32_t)__cvta_generic_to_shared(&sm.kv[buf][srow][scol]);
        cp16(dst,      src + scol);
        cp16(dst + 16, src + scol + 4);
        asm volatile("cp.async.commit_group;");
    };

    stage(0, 0);

    for (int t = 0; t < NTILE; t++) {
        if (t + 1 < NTILE) {
            stage(t+1, (t+1)&1);
            asm volatile("cp.async.wait_group 1;");
        } else {
            asm volatile("cp.async.wait_group 0;");
        }
        __syncthreads();

        bool isLocal = (t < 16);
        int wgl = t >> 2;
        // skip local tiles belonging to the other query-half's windows
        if (!isLocal || (wgl >> 1) == qh) {
            u64 mb = 0ull;
            if (isLocal) mb = pk2((wg == wgl) ? 0.f : -1e30f, 0.f);

            const float* kbase = &sm.kv[t&1][0][h*16];
#pragma unroll 4
            for (int j = 0; j < 16; j++) {
                const longlong2* kp = (const longlong2*)(kbase + j*256);
                longlong2 ka = kp[0], kb2 = kp[1], kc = kp[2], kd = kp[3];
                u64 d0 = ffma2(q[0], (u64)ka.x,  mb);
                d0 = ffma2(q[1], (u64)ka.y,  d0);
                d0 = ffma2(q[2], (u64)kb2.x, d0);
                d0 = ffma2(q[3], (u64)kb2.y, d0);
                d0 = ffma2(q[4], (u64)kc.x,  d0);
                d0 = ffma2(q[5], (u64)kc.y,  d0);
                d0 = ffma2(q[6], (u64)kd.x,  d0);
                d0 = ffma2(q[7], (u64)kd.y,  d0);
                float a, bb;
                up2(d0, a, bb);
                float p = ex2f(a + bb);
                ls += p;
                u64 P = pk2(p, p);

                const longlong2* vp = (const longlong2*)(kbase + j*256 + 128);
                longlong2 va = vp[0], vb2 = vp[1], vc = vp[2], vd = vp[3];
                acc[0] = ffma2(P, (u64)va.x,  acc[0]);
                acc[1] = ffma2(P, (u64)va.y,  acc[1]);
                acc[2] = ffma2(P, (u64)vb2.x, acc[2]);
                acc[3] = ffma2(P, (u64)vb2.y, acc[3]);
                acc[4] = ffma2(P, (u64)vc.x,  acc[4]);
                acc[5] = ffma2(P, (u64)vc.y,  acc[5]);
                acc[6] = ffma2(P, (u64)vd.x,  acc[6]);
                acc[7] = ffma2(P, (u64)vd.y,  acc[7]);
            }
        }
        __syncthreads();
    }

    // ---- normalize and park attended vectors in smem (epilogue union) ----
    {
        float inv = 1.f / ls;
        u64 INV = pk2(inv, inv);
        float* r = &sm.e.att[qg][h*16];
#pragma unroll
        for (int i = 0; i < 8; i++) {
            float a, bb;
            up2(fmul2(acc[i], INV), a, bb);
            r[2*i] = a; r[2*i+1] = bb;
        }
    }
    __syncthreads();

    // ---- out projection: thread = (aqi = tid>>3, og = tid&7) ----
    int aqi = tid >> 3, og = tid & 7;
    float o[16];
#pragma unroll 1
    for (int ch = 0; ch < 8; ch++) {
        {
            int row = tid >> 5, quad = tid & 31;
            *(float4*)&sm.e.w[row][quad*4] =
                *(const float4*)(ow + (size_t)(ch*16 + row)*128 + quad*4);
        }
        __syncthreads();
        u64 r0p = 0ull, r1p = 0ull;
#pragma unroll
        for (int k4 = 0; k4 < 32; k4++) {
            longlong2 av = *(const longlong2*)&sm.e.att[aqi][k4*4];
            longlong2 w0 = *(const longlong2*)&sm.e.w[og][k4*4];
            longlong2 w1 = *(const longlong2*)&sm.e.w[og+8][k4*4];
            r0p = ffma2((u64)av.x, (u64)w0.x, r0p);
            r0p = ffma2((u64)av.y, (u64)w0.y, r0p);
            r1p = ffma2((u64)av.x, (u64)w1.x, r1p);
            r1p = ffma2((u64)av.y, (u64)w1.y, r1p);
        }
        float a, bb;
        up2(r0p, a, bb); o[ch*2]   = a + bb;
        up2(r1p, a, bb); o[ch*2+1] = a + bb;
        __syncthreads();
    }

    // ---- residual add + NCHW scatter store ----
    {
        int qi = aqi & 15, wq = aqi >> 4;
        int wy = gy*2 + (wq>>1), wx = gx*2 + (wq&1);
        int py = wy*4 + (qi>>2), px = wx*4 + (qi&3);
#pragma unroll
        for (int ch = 0; ch < 8; ch++) {
#pragma unroll
            for (int u2 = 0; u2 < 2; u2++) {
                int oc = ch*16 + u2*8 + og;
                size_t gi = (((size_t)b*128 + oc)*48 + py)*48 + px;
                out[gi] = o[ch*2+u2] + ob[oc] + feat[gi];
            }
        }
    }
}

// ============================================================================
extern "C" void kernel_launch(void* const* d_in, const int* in_sizes, int n_in,
                              void* d_out, int out_size) {
    const float* feat = (const float*)d_in[0];
    const float* lnw  = (const float*)d_in[1];
    const float* lnb  = (const float*)d_in[2];
    const float* qw   = (const float*)d_in[3];
    const float* qb   = (const float*)d_in[4];
    const float* kvw  = (const float*)d_in[5];
    const float* kvb  = (const float*)d_in[6];
    const float* ow   = (const float*)d_in[7];
    const float* ob   = (const float*)d_in[8];
    float* out = (float*)d_out;

    k0_ln<<<1152, 256>>>(feat, lnw, lnb);
    k1_gemm<<<dim3(144, 3), 256>>>(qw, qb, kvw, kvb);
    k2_pool<<<2880, 256>>>();
    k3_attn<<<144, 512>>>(feat, kvb, ow, ob, out);
}

// round 5
// speedup vs baseline: 1.5913x; 1.0599x over previous
#include <cuda_runtime.h>
#include <cstdint>

// Problem constants
#define BB 4
#define HH 48
#define WW 48
#define CC 128
#define NWIN 144
#define NHEAD 8

typedef unsigned long long u64;

// ---------------- scratch (device globals; no allocation allowed) ----------
__device__ float g_F [BB*HH*WW*CC];      // raw features, pixel-major
__device__ float g_FN[BB*HH*WW*CC];      // layernormed features, pixel-major
__device__ float g_Q [BB*HH*WW*CC];      // queries per pixel
__device__ float g_KV[BB*HH*WW*256];     // per-pixel KV projection (K|V)
__device__ float g_KVmid[BB*24*24*256];  // 2x2 pooled KV
__device__ float g_KVglo[BB*12*12*256];  // 4x4 pooled KV

__device__ __forceinline__ float ex2f(float x) {
    float r; asm("ex2.approx.f32 %0, %1;" : "=f"(r) : "f"(x)); return r;
}
__device__ __forceinline__ u64 ffma2(u64 a, u64 b, u64 c) {
    u64 d; asm("fma.rn.f32x2 %0,%1,%2,%3;" : "=l"(d) : "l"(a), "l"(b), "l"(c)); return d;
}
__device__ __forceinline__ u64 fmul2(u64 a, u64 b) {
    u64 d; asm("mul.rn.f32x2 %0,%1,%2;" : "=l"(d) : "l"(a), "l"(b)); return d;
}
__device__ __forceinline__ u64 pk2(float lo, float hi) {
    u64 d; asm("mov.b64 %0,{%1,%2};" : "=l"(d) : "f"(lo), "f"(hi)); return d;
}
__device__ __forceinline__ void up2(u64 v, float& lo, float& hi) {
    asm("mov.b64 {%0,%1},%2;" : "=f"(lo), "=f"(hi) : "l"(v));
}
__device__ __forceinline__ void cp16(uint32_t dst, const float* src) {
    asm volatile("cp.async.cg.shared.global [%0], [%1], 16;" :: "r"(dst), "l"(src));
}

// ============================================================================
// Kernel 0: transpose NCHW -> pixel-major + LayerNorm.  One warp per pixel.
// ============================================================================
__global__ void k0_ln(const float* __restrict__ feat,
                      const float* __restrict__ lnw,
                      const float* __restrict__ lnb) {
    int warp = (blockIdx.x * blockDim.x + threadIdx.x) >> 5;
    int lane = threadIdx.x & 31;
    if (warp >= BB*HH*WW) return;
    int b   = warp / (HH*WW);
    int rem = warp % (HH*WW);
    const float* src = feat + (size_t)b * CC * HH * WW + rem;

    float v[4];
    float s = 0.f, ss = 0.f;
#pragma unroll
    for (int i = 0; i < 4; i++) {
        int c = lane + 32*i;
        v[i] = src[(size_t)c * (HH*WW)];
        s  += v[i];
        ss += v[i]*v[i];
    }
#pragma unroll
    for (int o = 16; o; o >>= 1) {
        s  += __shfl_xor_sync(0xffffffffu, s,  o);
        ss += __shfl_xor_sync(0xffffffffu, ss, o);
    }
    float mean = s * (1.f/128.f);
    float var  = ss * (1.f/128.f) - mean*mean;
    float rstd = rsqrtf(var + 1e-5f);

    float* dF = g_F  + (size_t)warp * CC;
    float* dN = g_FN + (size_t)warp * CC;
#pragma unroll
    for (int i = 0; i < 4; i++) {
        int c = lane + 32*i;
        dF[c] = v[i];
        dN[c] = (v[i] - mean) * rstd * lnw[c] + lnb[c];
    }
}

// ============================================================================
// Kernel 1: fused GEMMs (Q / K / V projections).  Unchanged.
// ============================================================================
#define MT 64
#define PADK 36

__global__ void k1_gemm(const float* __restrict__ qw, const float* __restrict__ qb,
                        const float* __restrict__ kvw, const float* __restrict__ kvb) {
    __shared__ float sA[MT][PADK];
    __shared__ float sB[128][PADK];

    int sub   = blockIdx.y;
    int mBase = blockIdx.x * MT;
    const float* A    = (sub == 0) ? g_FN : g_F;
    const float* Wm   = (sub == 0) ? qw : (kvw + (size_t)(sub-1)*128*128);
    const float* bias = (sub == 0) ? qb : (kvb + (sub-1)*128);

    int tid = threadIdx.x;
    int mg = tid & 15;
    int ng = tid >> 4;

    float acc[4][8];
#pragma unroll
    for (int m = 0; m < 4; m++)
#pragma unroll
        for (int n = 0; n < 8; n++) acc[m][n] = 0.f;

    for (int ck = 0; ck < 4; ck++) {
        __syncthreads();
#pragma unroll
        for (int i = 0; i < 2; i++) {
            int f = tid + i*256;
            int pix = f >> 3, kq = f & 7;
            float4 val = *(const float4*)(A + (size_t)(mBase+pix)*128 + ck*32 + kq*4);
            *(float4*)&sA[pix][kq*4] = val;
        }
#pragma unroll
        for (int i = 0; i < 4; i++) {
            int f = tid + i*256;
            int row = f >> 3, kq = f & 7;
            float4 val = *(const float4*)(Wm + (size_t)row*128 + ck*32 + kq*4);
            *(float4*)&sB[row][kq*4] = val;
        }
        __syncthreads();

#pragma unroll
        for (int k4 = 0; k4 < 8; k4++) {
            float4 a0 = *(const float4*)&sA[mg*4+0][k4*4];
            float4 a1 = *(const float4*)&sA[mg*4+1][k4*4];
            float4 a2 = *(const float4*)&sA[mg*4+2][k4*4];
            float4 a3 = *(const float4*)&sA[mg*4+3][k4*4];
#pragma unroll
            for (int n = 0; n < 8; n++) {
                float4 bv = *(const float4*)&sB[ng*8+n][k4*4];
                acc[0][n] += a0.x*bv.x + a0.y*bv.y + a0.z*bv.z + a0.w*bv.w;
                acc[1][n] += a1.x*bv.x + a1.y*bv.y + a1.z*bv.z + a1.w*bv.w;
                acc[2][n] += a2.x*bv.x + a2.y*bv.y + a2.z*bv.z + a2.w*bv.w;
                acc[3][n] += a3.x*bv.x + a3.y*bv.y + a3.z*bv.z + a3.w*bv.w;
            }
        }
    }

    float4 bv0 = *(const float4*)(bias + ng*8);
    float4 bv1 = *(const float4*)(bias + ng*8 + 4);
    int stride = (sub == 0) ? 128 : 256;
    float* base = (sub == 0) ? (g_Q + ng*8) : (g_KV + (sub-1)*128 + ng*8);
#pragma unroll
    for (int m = 0; m < 4; m++) {
        float* dst = base + (size_t)(mBase + mg*4 + m) * stride;
        float4 r0 = make_float4(acc[m][0]+bv0.x, acc[m][1]+bv0.y, acc[m][2]+bv0.z, acc[m][3]+bv0.w);
        float4 r1 = make_float4(acc[m][4]+bv1.x, acc[m][5]+bv1.y, acc[m][6]+bv1.z, acc[m][7]+bv1.w);
        *(float4*)dst       = r0;
        *((float4*)dst + 1) = r1;
    }
}

// ============================================================================
// Kernel 2: pooled KV.  Unchanged.
// ============================================================================
__global__ void k2_pool() {
    int t = blockIdx.x;
    int c = threadIdx.x;
    if (t < BB*576) {
        int b = t / 576, r = t % 576, my = r / 24, mx = r % 24;
        const float* base = g_KV + ((size_t)((b*48 + my*2)*48 + mx*2))*256 + c;
        float v = base[0] + base[256] + base[48*256] + base[48*256 + 256];
        g_KVmid[(size_t)t*256 + c] = v * 0.25f;
    } else {
        int t2 = t - BB*576;
        int b = t2 / 144, r = t2 % 144, gy = r / 12, gx = r % 12;
        float v = 0.f;
#pragma unroll
        for (int i = 0; i < 4; i++)
#pragma unroll
            for (int j = 0; j < 4; j++)
                v += g_KV[((size_t)((b*48 + gy*4 + i)*48 + gx*4 + j))*256 + c];
        g_KVglo[(size_t)t2*256 + c] = v * (1.f/16.f);
    }
}

// ============================================================================
// Kernel 3 v4: 2x2 window group, cp.async staging, 2 QUERIES PER LANE,
//   token-parity split between the two warp halves.
//   16 warps = 8 heads x 2 token-halves.  Lane owns queries (lane, lane+32).
//   Each staged K/V vector feeds 4 FFMA2 -> LDS:FMA pipes balanced.
//   Partial acc/lsum of the two halves merged via smem; fused out-proj.
// ============================================================================
#define NTILE 61

__global__ void __launch_bounds__(512, 1)
k3_attn(const float* __restrict__ feat, const float* __restrict__ kvb,
        const float* __restrict__ ow,   const float* __restrict__ ob,
        float* __restrict__ out) {
    __shared__ union {
        float kv[2][16][256];                        // 32 KB (mainloop ring)
        struct {
            float att[64][132];                      // 33 KB
            float l[64][8];                          //  2 KB
            float w[16][132];                        //  8.25 KB
        } e;                                         // 44.3 KB (epilogue)
    } sm;

    int cta = blockIdx.x;
    int b = cta / 36, g = cta % 36;
    int gy = g / 6, gx = g % 6;
    int tid  = threadIdx.x;
    int lane = tid & 31;
    int warp = tid >> 5;
    int h = warp & 7, th = warp >> 3;     // head, token-half (tile parity)

    int qg0 = lane, qg1 = lane + 32;
    int wgA = qg0 >> 4, wgB = qg1 >> 4;   // window-in-group of each query

    const float SC = 0.25f * 1.4426950408889634f;
    u64 SC2 = pk2(SC, SC);

    // ---- load 2 queries (16 dims each), pre-scaled ----
    u64 q0[8], q1[8];
    {
        int qi = qg0 & 15;
        int wy = gy*2 + (wgA>>1), wx = gx*2 + (wgA&1);
        int py = wy*4 + (qi>>2), px = wx*4 + (qi&3);
        const longlong2* qp = (const longlong2*)(g_Q + ((size_t)((b*48+py)*48+px))*128 + h*16);
#pragma unroll
        for (int i = 0; i < 4; i++) {
            longlong2 t2 = qp[i];
            q0[2*i]   = fmul2((u64)t2.x, SC2);
            q0[2*i+1] = fmul2((u64)t2.y, SC2);
        }
    }
    {
        int qi = qg1 & 15;
        int wy = gy*2 + (wgB>>1), wx = gx*2 + (wgB&1);
        int py = wy*4 + (qi>>2), px = wx*4 + (qi&3);
        const longlong2* qp = (const longlong2*)(g_Q + ((size_t)((b*48+py)*48+px))*128 + h*16);
#pragma unroll
        for (int i = 0; i < 4; i++) {
            longlong2 t2 = qp[i];
            q1[2*i]   = fmul2((u64)t2.x, SC2);
            q1[2*i+1] = fmul2((u64)t2.y, SC2);
        }
    }

    u64 acc0[8], acc1[8];
#pragma unroll
    for (int i = 0; i < 8; i++) { acc0[i] = 0ull; acc1[i] = 0ull; }
    float ls0 = 0.f, ls1 = 0.f;

    // staging role: 32 threads per token row, 8 floats (32 B) each
    int srow = tid >> 5;
    int scol = (tid & 31) * 8;

    auto stage = [&](int tt, int buf) {
        const float* src;
        if (tt < 16) {
            int wgl = tt >> 2, st = tt & 3;
            int idx = st*16 + srow;
            int y = (gy*2 + (wgl>>1))*4 + (idx>>3) - 2;
            int x = (gx*2 + (wgl&1))*4  + (idx&7)  - 2;
            src = ((unsigned)y < 48u && (unsigned)x < 48u)
                ? (g_KV + ((size_t)((b*48+y)*48+x))*256) : kvb;
        } else if (tt < 52) {
            src = g_KVmid + ((size_t)(b*576 + (tt-16)*16 + srow))*256;
        } else {
            src = g_KVglo + ((size_t)(b*144 + (tt-52)*16 + srow))*256;
        }
        uint32_t dst = (uint32_t)__cvta_generic_to_shared(&sm.kv[buf][srow][scol]);
        cp16(dst,      src + scol);
        cp16(dst + 16, src + scol + 4);
        asm volatile("cp.async.commit_group;");
    };

    stage(0, 0);

    for (int t = 0; t < NTILE; t++) {
        if (t + 1 < NTILE) {
            stage(t+1, (t+1)&1);
            asm volatile("cp.async.wait_group 1;");
        } else {
            asm volatile("cp.async.wait_group 0;");
        }
        __syncthreads();

        // this warp-half computes tiles of its parity only
        if ((t & 1) == th) {
            bool isLocal = (t < 16);
            int wgl = t >> 2;
            u64 mb0 = 0ull, mb1 = 0ull;
            if (isLocal) {
                mb0 = pk2((wgA == wgl) ? 0.f : -1e30f, 0.f);
                mb1 = pk2((wgB == wgl) ? 0.f : -1e30f, 0.f);
            }

            const float* kbase = &sm.kv[t&1][0][h*16];
#pragma unroll 4
            for (int j = 0; j < 16; j++) {
                const longlong2* kp = (const longlong2*)(kbase + j*256);
                longlong2 ka = kp[0], kb2 = kp[1], kc = kp[2], kd = kp[3];
                u64 d0 = ffma2(q0[0], (u64)ka.x,  mb0);
                d0 = ffma2(q0[1], (u64)ka.y,  d0);
                d0 = ffma2(q0[2], (u64)kb2.x, d0);
                d0 = ffma2(q0[3], (u64)kb2.y, d0);
                d0 = ffma2(q0[4], (u64)kc.x,  d0);
                d0 = ffma2(q0[5], (u64)kc.y,  d0);
                d0 = ffma2(q0[6], (u64)kd.x,  d0);
                d0 = ffma2(q0[7], (u64)kd.y,  d0);
                u64 d1 = ffma2(q1[0], (u64)ka.x,  mb1);
                d1 = ffma2(q1[1], (u64)ka.y,  d1);
                d1 = ffma2(q1[2], (u64)kb2.x, d1);
                d1 = ffma2(q1[3], (u64)kb2.y, d1);
                d1 = ffma2(q1[4], (u64)kc.x,  d1);
                d1 = ffma2(q1[5], (u64)kc.y,  d1);
                d1 = ffma2(q1[6], (u64)kd.x,  d1);
                d1 = ffma2(q1[7], (u64)kd.y,  d1);

                float a, bb;
                up2(d0, a, bb); float p0 = ex2f(a + bb);
                up2(d1, a, bb); float p1 = ex2f(a + bb);
                ls0 += p0; ls1 += p1;
                u64 P0 = pk2(p0, p0), P1 = pk2(p1, p1);

                const longlong2* vp = (const longlong2*)(kbase + j*256 + 128);
                longlong2 va = vp[0], vb2 = vp[1], vc = vp[2], vd = vp[3];
                acc0[0] = ffma2(P0, (u64)va.x,  acc0[0]);
                acc0[1] = ffma2(P0, (u64)va.y,  acc0[1]);
                acc0[2] = ffma2(P0, (u64)vb2.x, acc0[2]);
                acc0[3] = ffma2(P0, (u64)vb2.y, acc0[3]);
                acc0[4] = ffma2(P0, (u64)vc.x,  acc0[4]);
                acc0[5] = ffma2(P0, (u64)vc.y,  acc0[5]);
                acc0[6] = ffma2(P0, (u64)vd.x,  acc0[6]);
                acc0[7] = ffma2(P0, (u64)vd.y,  acc0[7]);
                acc1[0] = ffma2(P1, (u64)va.x,  acc1[0]);
                acc1[1] = ffma2(P1, (u64)va.y,  acc1[1]);
                acc1[2] = ffma2(P1, (u64)vb2.x, acc1[2]);
                acc1[3] = ffma2(P1, (u64)vb2.y, acc1[3]);
                acc1[4] = ffma2(P1, (u64)vc.x,  acc1[4]);
                acc1[5] = ffma2(P1, (u64)vc.y,  acc1[5]);
                acc1[6] = ffma2(P1, (u64)vd.x,  acc1[6]);
                acc1[7] = ffma2(P1, (u64)vd.y,  acc1[7]);
            }
        }
        __syncthreads();
    }

    // ---- merge the two token-halves via smem, normalize ----
    if (th == 0) {
        float* r0 = &sm.e.att[qg0][h*16];
        float* r1 = &sm.e.att[qg1][h*16];
#pragma unroll
        for (int i = 0; i < 8; i++) {
            float a, bb;
            up2(acc0[i], a, bb); r0[2*i] = a; r0[2*i+1] = bb;
            up2(acc1[i], a, bb); r1[2*i] = a; r1[2*i+1] = bb;
        }
        sm.e.l[qg0][h] = ls0;
        sm.e.l[qg1][h] = ls1;
    }
    __syncthreads();
    if (th == 1) {
        float inv0 = 1.f / (sm.e.l[qg0][h] + ls0);
        float inv1 = 1.f / (sm.e.l[qg1][h] + ls1);
        float* r0 = &sm.e.att[qg0][h*16];
        float* r1 = &sm.e.att[qg1][h*16];
#pragma unroll
        for (int i = 0; i < 8; i++) {
            float a, bb;
            up2(acc0[i], a, bb);
            r0[2*i]   = (r0[2*i]   + a ) * inv0;
            r0[2*i+1] = (r0[2*i+1] + bb) * inv0;
            up2(acc1[i], a, bb);
            r1[2*i]   = (r1[2*i]   + a ) * inv1;
            r1[2*i+1] = (r1[2*i+1] + bb) * inv1;
        }
    }
    __syncthreads();

    // ---- out projection: thread = (aqi = tid>>3, og = tid&7) ----
    int aqi = tid >> 3, og = tid & 7;
    float o[16];
#pragma unroll 1
    for (int ch = 0; ch < 8; ch++) {
        {
            int row = tid >> 5, quad = tid & 31;
            *(float4*)&sm.e.w[row][quad*4] =
                *(const float4*)(ow + (size_t)(ch*16 + row)*128 + quad*4);
        }
        __syncthreads();
        u64 r0p = 0ull, r1p = 0ull;
#pragma unroll
        for (int k4 = 0; k4 < 32; k4++) {
            longlong2 av = *(const longlong2*)&sm.e.att[aqi][k4*4];
            longlong2 w0 = *(const longlong2*)&sm.e.w[og][k4*4];
            longlong2 w1 = *(const longlong2*)&sm.e.w[og+8][k4*4];
            r0p = ffma2((u64)av.x, (u64)w0.x, r0p);
            r0p = ffma2((u64)av.y, (u64)w0.y, r0p);
            r1p = ffma2((u64)av.x, (u64)w1.x, r1p);
            r1p = ffma2((u64)av.y, (u64)w1.y, r1p);
        }
        float a, bb;
        up2(r0p, a, bb); o[ch*2]   = a + bb;
        up2(r1p, a, bb); o[ch*2+1] = a + bb;
        __syncthreads();
    }

    // ---- residual add + NCHW scatter store ----
    {
        int qi = aqi & 15, wq = aqi >> 4;
        int wy = gy*2 + (wq>>1), wx = gx*2 + (wq&1);
        int py = wy*4 + (qi>>2), px = wx*4 + (qi&3);
#pragma unroll
        for (int ch = 0; ch < 8; ch++) {
#pragma unroll
            for (int u2 = 0; u2 < 2; u2++) {
                int oc = ch*16 + u2*8 + og;
                size_t gi = (((size_t)b*128 + oc)*48 + py)*48 + px;
                out[gi] = o[ch*2+u2] + ob[oc] + feat[gi];
            }
        }
    }
}

// ============================================================================
extern "C" void kernel_launch(void* const* d_in, const int* in_sizes, int n_in,
                              void* d_out, int out_size) {
    const float* feat = (const float*)d_in[0];
    const float* lnw  = (const float*)d_in[1];
    const float* lnb  = (const float*)d_in[2];
    const float* qw   = (const float*)d_in[3];
    const float* qb   = (const float*)d_in[4];
    const float* kvw  = (const float*)d_in[5];
    const float* kvb  = (const float*)d_in[6];
    const float* ow   = (const float*)d_in[7];
    const float* ob   = (const float*)d_in[8];
    float* out = (float*)d_out;

    k0_ln<<<1152, 256>>>(feat, lnw, lnb);
    k1_gemm<<<dim3(144, 3), 256>>>(qw, qb, kvw, kvb);
    k2_pool<<<2880, 256>>>();
    k3_attn<<<144, 512>>>(feat, kvb, ow, ob, out);
}